// round 4
// baseline (speedup 1.0000x reference)
#include <cuda_runtime.h>
#include <cuda_bf16.h>
#include <cstdint>
#include <cstddef>

#define BB 128
#define TT 2048
#define II 64
#define HH 128
#define GG 512                 // 4*H
#define BT (BB * TT)
#define REGK 80                // W_hh cols held in registers per thread
#define SMEMK (HH - REGK)      // 48 cols in SMEM
#define NSK (SMEMK / 4)        // 12 float4 groups

typedef unsigned long long u64;

// 512MB scratch for x_proj[row][g], row = b*T + t, g in [0,512)
__device__ float g_xproj[(size_t)BT * GG];

__device__ __forceinline__ u64 pk(float lo, float hi) {
    u64 r; asm("mov.b64 %0,{%1,%2};" : "=l"(r) : "f"(lo), "f"(hi)); return r;
}
__device__ __forceinline__ void upk(u64 v, float& lo, float& hi) {
    asm("mov.b64 {%0,%1},%2;" : "=f"(lo), "=f"(hi) : "l"(v));
}
// packed fp32x2 FMA (sm_103a): d.lo += a.lo*b.lo ; d.hi += a.hi*b.hi
__device__ __forceinline__ void fma2(u64& d, u64 a, u64 b) {
    asm("fma.rn.f32x2 %0,%1,%2,%0;" : "+l"(d) : "l"(a), "l"(b));
}

__device__ __forceinline__ float sigmoidf_(float x) {
    return 1.0f / (1.0f + __expf(-x));
}
__device__ __forceinline__ float tanhf_(float x) {
    float xc = fminf(fmaxf(x, -15.0f), 15.0f);
    float e = __expf(-2.0f * xc);
    return (1.0f - e) / (1.0f + e);
}

// ---------------------------------------------------------------------------
// Phase 1: g_xproj[row][512] = W_ih @ x[row] + (b_ih + b_hh)
// Persistent CTAs; W_ih k-major in SMEM; 64-row x tiles k-major in SMEM.
// Each thread: 8 rows x 8 cols via packed f32x2 FMA.
// Dynamic SMEM: wsg 64*512*4 = 131072, bsum 2048, xs 64*68*4 = 17408 -> 150528B
// ---------------------------------------------------------------------------
__global__ __launch_bounds__(512, 1) void xproj_kernel(
    const float* __restrict__ x, const float* __restrict__ Wih,
    const float* __restrict__ bih, const float* __restrict__ bhh)
{
    extern __shared__ float sm1[];
    float* wsg  = sm1;                   // [64][512] k-major
    float* bsum = wsg + 64 * 512;        // [512]
    float* xs   = bsum + 512;            // [64 k][68 rows] padded

    const int tid = threadIdx.x;

    // W_ih transposed into SMEM: wsg[k*512 + c] = Wih[c][k]
    for (int idx = tid; idx < 64 * 512; idx += 512) {
        int k = idx >> 9, c = idx & 511;
        wsg[idx] = Wih[c * 64 + k];
    }
    bsum[tid] = bih[tid] + bhh[tid];
    __syncthreads();

    const int lane = tid & 31, wrp = tid >> 5;
    const int r0 = (wrp & 7) * 8;                    // 8 rows per thread
    const int cb = (wrp >> 3) * 256 + lane * 4;      // cols cb..cb+3, cb+128..cb+131

    u64 bp[4];
    {
        float4 t0 = *(const float4*)&bsum[cb];
        float4 t1 = *(const float4*)&bsum[cb + 128];
        bp[0] = pk(t0.x, t0.y); bp[1] = pk(t0.z, t0.w);
        bp[2] = pk(t1.x, t1.y); bp[3] = pk(t1.z, t1.w);
    }

    for (int tile = blockIdx.x; tile < BT / 64; tile += gridDim.x) {
        __syncthreads();   // protect xs from previous tile's readers
        // stage x tile (64 rows x 64 k) transposed to k-major, pad 68
        for (int idx = tid; idx < 64 * 64; idx += 512) {
            int r = idx >> 6, k = idx & 63;
            xs[k * 68 + r] = x[(size_t)tile * 64 * 64 + idx];
        }
        __syncthreads();

        u64 acc[8][4];
        #pragma unroll
        for (int ri = 0; ri < 8; ri++) {
            acc[ri][0] = bp[0]; acc[ri][1] = bp[1];
            acc[ri][2] = bp[2]; acc[ri][3] = bp[3];
        }

        #pragma unroll 8
        for (int k = 0; k < 64; k++) {
            float4 w0 = *(const float4*)&wsg[k * 512 + cb];
            float4 w1 = *(const float4*)&wsg[k * 512 + cb + 128];
            u64 wa = pk(w0.x, w0.y), wb = pk(w0.z, w0.w);
            u64 wc = pk(w1.x, w1.y), wd = pk(w1.z, w1.w);
            float4 xa = *(const float4*)&xs[k * 68 + r0];
            float4 xb = *(const float4*)&xs[k * 68 + r0 + 4];
            float xv[8] = {xa.x, xa.y, xa.z, xa.w, xb.x, xb.y, xb.z, xb.w};
            #pragma unroll
            for (int ri = 0; ri < 8; ri++) {
                u64 xx = pk(xv[ri], xv[ri]);
                fma2(acc[ri][0], wa, xx); fma2(acc[ri][1], wb, xx);
                fma2(acc[ri][2], wc, xx); fma2(acc[ri][3], wd, xx);
            }
        }

        #pragma unroll
        for (int ri = 0; ri < 8; ri++) {
            size_t row = (size_t)tile * 64 + r0 + ri;
            float a0,a1,a2,a3,a4,a5,a6,a7;
            upk(acc[ri][0], a0, a1); upk(acc[ri][1], a2, a3);
            upk(acc[ri][2], a4, a5); upk(acc[ri][3], a6, a7);
            *(float4*)&g_xproj[row * GG + cb]       = make_float4(a0,a1,a2,a3);
            *(float4*)&g_xproj[row * GG + cb + 128] = make_float4(a4,a5,a6,a7);
        }
    }
}

// ---------------------------------------------------------------------------
// Phase 2: LSTM recurrence. One CTA per batch element (128 CTAs, one wave).
// Thread j owns gate row j: W_hh[j][0:80] in regs, W_hh[j][80:128] in SMEM
// (transposed float4 layout [NSK][512] -> conflict-free LDS.128).
// h broadcast from SMEM double buffer; x_proj prefetched one step ahead.
// Dynamic SMEM: ws4 12*512*16 = 98304, h 2*128*4 = 1024, gates 512*4 = 2048
//             -> 101376B
// ---------------------------------------------------------------------------
__global__ __launch_bounds__(512, 1) void lstm_kernel(
    const float* __restrict__ Whh, const float* __restrict__ h0,
    const float* __restrict__ c0, float* __restrict__ out)
{
    extern __shared__ float sm2[];
    float4* ws4   = (float4*)sm2;              // [NSK][512]
    float*  h_s   = sm2 + NSK * 512 * 4;       // [2][128]
    float*  gates = h_s + 2 * HH;              // [512]

    const int j = threadIdx.x;
    const int b = blockIdx.x;

    // --- load register-resident weights: W_hh[j][0:80] as 40 packed pairs ---
    u64 wreg[REGK / 2];
    {
        const float* wrow = Whh + j * HH;
        #pragma unroll
        for (int kk = 0; kk < REGK / 4; kk++) {
            float4 w = *(const float4*)&wrow[4 * kk];
            wreg[2 * kk]     = pk(w.x, w.y);
            wreg[2 * kk + 1] = pk(w.z, w.w);
        }
    }
    // --- SMEM weights: ws4[kk][j] = W_hh[j][80+4kk .. +3] ---
    for (int idx = j; idx < NSK * 512; idx += 512) {
        int kk = idx >> 9, r = idx & 511;
        ws4[idx] = *(const float4*)&Whh[r * HH + REGK + 4 * kk];
    }
    // --- initial state ---
    float c = 0.0f;
    if (j < HH) {
        h_s[j] = h0[b * HH + j];
        c = c0[b * HH + j];
    }
    __syncthreads();

    const float* xp = g_xproj + (size_t)b * TT * GG;
    float* enc = out + BB * HH + (size_t)b * TT * HH;

    int p = 0;
    float xg = xp[j];                 // prefetch t = 0
    for (int t = 0; t < TT; t++) {
        float xg_cur = xg;
        if (t + 1 < TT) xg = xp[(size_t)(t + 1) * GG + j];   // prefetch next

        const float* hb = &h_s[p * HH];
        u64 acc0 = 0ULL, acc1 = 0ULL;
        // register-weight part, k in [0, 80)
        #pragma unroll
        for (int kk = 0; kk < REGK / 4; kk++) {
            float4 h4 = *(const float4*)&hb[4 * kk];           // broadcast
            fma2(acc0, wreg[2 * kk],     pk(h4.x, h4.y));
            fma2(acc1, wreg[2 * kk + 1], pk(h4.z, h4.w));
        }
        // SMEM-weight part, k in [80, 128)
        #pragma unroll
        for (int kk = 0; kk < NSK; kk++) {
            float4 w4 = ws4[kk * 512 + j];
            float4 h4 = *(const float4*)&hb[REGK + 4 * kk];    // broadcast
            fma2(acc0, pk(w4.x, w4.y), pk(h4.x, h4.y));
            fma2(acc1, pk(w4.z, w4.w), pk(h4.z, h4.w));
        }
        float l0, l1, l2, l3;
        upk(acc0, l0, l1); upk(acc1, l2, l3);
        gates[j] = xg_cur + (l0 + l1) + (l2 + l3);
        __syncthreads();

        if (j < HH) {
            float ig = sigmoidf_(gates[j]);
            float fg = sigmoidf_(gates[j + HH]);
            float gg = tanhf_   (gates[j + 2 * HH]);
            float og = sigmoidf_(gates[j + 3 * HH]);
            c = fg * c + ig * gg;
            float hn = og * tanhf_(c);
            h_s[(p ^ 1) * HH + j] = hn;
            enc[(size_t)t * HH + j] = hn;
        }
        __syncthreads();
        p ^= 1;
    }

    if (j < HH) out[b * HH + j] = h_s[p * HH + j];   // h_last
}

extern "C" void kernel_launch(void* const* d_in, const int* in_sizes, int n_in,
                              void* d_out, int out_size) {
    const float* x    = (const float*)d_in[0];   // [B,T,I]
    const float* h0   = (const float*)d_in[1];   // [B,H]
    const float* c0   = (const float*)d_in[2];   // [B,H]
    const float* Wih  = (const float*)d_in[3];   // [4H,I]
    const float* Whh  = (const float*)d_in[4];   // [4H,H]
    const float* bih  = (const float*)d_in[5];   // [4H]
    const float* bhh  = (const float*)d_in[6];   // [4H]
    float* out = (float*)d_out;                  // [B*H] h_last, then [B,T,H]

    constexpr int SMEM1 = (64 * 512 + 512 + 64 * 68) * 4;   // 150528
    constexpr int SMEM2 = (NSK * 512 * 4 + 2 * HH + 512) * 4; // 101376

    static bool attr_done = false;
    if (!attr_done) {
        cudaFuncSetAttribute(xproj_kernel,
            cudaFuncAttributeMaxDynamicSharedMemorySize, SMEM1);
        cudaFuncSetAttribute(lstm_kernel,
            cudaFuncAttributeMaxDynamicSharedMemorySize, SMEM2);
        attr_done = true;
    }

    xproj_kernel<<<148, 512, SMEM1>>>(x, Wih, bih, bhh);
    lstm_kernel<<<BB, 512, SMEM2>>>(Whh, h0, c0, out);
}

// round 8
// speedup vs baseline: 1.4832x; 1.4832x over previous
#include <cuda_runtime.h>
#include <cuda_bf16.h>
#include <cstdint>
#include <cstddef>

#define BB 128
#define TT 2048
#define II 64
#define HH 128
#define GG 512                 // 4*H
#define BT (BB * TT)

// ---- recurrence config: 256 threads, 2 rows/thread --------------------------
#define REGK 104               // W_hh cols per row held in registers
#define SMEMK (HH - REGK)      // 24 cols in SMEM
#define NSK (SMEMK / 2)        // 12 u64 groups per row

typedef unsigned long long u64;

// 512MB scratch for x_proj[row][g], row = b*T + t, g in [0,512)
__device__ float g_xproj[(size_t)BT * GG];

__device__ __forceinline__ u64 pk(float lo, float hi) {
    u64 r; asm("mov.b64 %0,{%1,%2};" : "=l"(r) : "f"(lo), "f"(hi)); return r;
}
__device__ __forceinline__ void upk(u64 v, float& lo, float& hi) {
    asm("mov.b64 {%0,%1},%2;" : "=f"(lo), "=f"(hi) : "l"(v));
}
// packed fp32x2 FMA (sm_103a): d.lo += a.lo*b.lo ; d.hi += a.hi*b.hi
__device__ __forceinline__ void fma2(u64& d, u64 a, u64 b) {
    asm("fma.rn.f32x2 %0,%1,%2,%0;" : "+l"(d) : "l"(a), "l"(b));
}

__device__ __forceinline__ float sigmoidf_(float x) {
    return 1.0f / (1.0f + __expf(-x));
}
__device__ __forceinline__ float tanhf_(float x) {
    float xc = fminf(fmaxf(x, -15.0f), 15.0f);
    float e = __expf(-2.0f * xc);
    return (1.0f - e) / (1.0f + e);
}

// ---------------------------------------------------------------------------
// Phase 1: g_xproj[row][512] = W_ih @ x[row] + (b_ih + b_hh)
// Persistent CTAs; W_ih k-major in SMEM; 64-row x tiles k-major in SMEM.
// Each thread: 8 rows x 8 cols via packed f32x2 FMA.
// ---------------------------------------------------------------------------
__global__ __launch_bounds__(512, 1) void xproj_kernel(
    const float* __restrict__ x, const float* __restrict__ Wih,
    const float* __restrict__ bih, const float* __restrict__ bhh)
{
    extern __shared__ float sm1[];
    float* wsg  = sm1;                   // [64][512] k-major
    float* bsum = wsg + 64 * 512;        // [512]
    float* xs   = bsum + 512;            // [64 k][68 rows] padded

    const int tid = threadIdx.x;

    for (int idx = tid; idx < 64 * 512; idx += 512) {
        int k = idx >> 9, c = idx & 511;
        wsg[idx] = Wih[c * 64 + k];
    }
    bsum[tid] = bih[tid] + bhh[tid];
    __syncthreads();

    const int lane = tid & 31, wrp = tid >> 5;
    const int r0 = (wrp & 7) * 8;
    const int cb = (wrp >> 3) * 256 + lane * 4;

    u64 bp[4];
    {
        float4 t0 = *(const float4*)&bsum[cb];
        float4 t1 = *(const float4*)&bsum[cb + 128];
        bp[0] = pk(t0.x, t0.y); bp[1] = pk(t0.z, t0.w);
        bp[2] = pk(t1.x, t1.y); bp[3] = pk(t1.z, t1.w);
    }

    for (int tile = blockIdx.x; tile < BT / 64; tile += gridDim.x) {
        __syncthreads();
        for (int idx = tid; idx < 64 * 64; idx += 512) {
            int r = idx >> 6, k = idx & 63;
            xs[k * 68 + r] = x[(size_t)tile * 64 * 64 + idx];
        }
        __syncthreads();

        u64 acc[8][4];
        #pragma unroll
        for (int ri = 0; ri < 8; ri++) {
            acc[ri][0] = bp[0]; acc[ri][1] = bp[1];
            acc[ri][2] = bp[2]; acc[ri][3] = bp[3];
        }

        #pragma unroll 8
        for (int k = 0; k < 64; k++) {
            float4 w0 = *(const float4*)&wsg[k * 512 + cb];
            float4 w1 = *(const float4*)&wsg[k * 512 + cb + 128];
            u64 wa = pk(w0.x, w0.y), wb = pk(w0.z, w0.w);
            u64 wc = pk(w1.x, w1.y), wd = pk(w1.z, w1.w);
            float4 xa = *(const float4*)&xs[k * 68 + r0];
            float4 xb = *(const float4*)&xs[k * 68 + r0 + 4];
            float xv[8] = {xa.x, xa.y, xa.z, xa.w, xb.x, xb.y, xb.z, xb.w};
            #pragma unroll
            for (int ri = 0; ri < 8; ri++) {
                u64 xx = pk(xv[ri], xv[ri]);
                fma2(acc[ri][0], wa, xx); fma2(acc[ri][1], wb, xx);
                fma2(acc[ri][2], wc, xx); fma2(acc[ri][3], wd, xx);
            }
        }

        #pragma unroll
        for (int ri = 0; ri < 8; ri++) {
            size_t row = (size_t)tile * 64 + r0 + ri;
            float a0,a1,a2,a3,a4,a5,a6,a7;
            upk(acc[ri][0], a0, a1); upk(acc[ri][1], a2, a3);
            upk(acc[ri][2], a4, a5); upk(acc[ri][3], a6, a7);
            *(float4*)&g_xproj[row * GG + cb]       = make_float4(a0,a1,a2,a3);
            *(float4*)&g_xproj[row * GG + cb + 128] = make_float4(a4,a5,a6,a7);
        }
    }
}

// ---------------------------------------------------------------------------
// Phase 2: LSTM recurrence. One CTA per batch (128 CTAs, one wave).
// 256 threads; thread tid owns gate rows tid and tid+256, so thread tid and
// tid+128 together hold all 4 gates of hidden unit jh = tid & 127.
// W_hh[row][0:104] in registers (2 x 52 u64), [104:128) in SMEM as u64 pairs.
// h broadcast from SMEM double buffer as u64 pairs, reused by both rows.
// Activations distributed pre-barrier; phase B redundant across partner pair.
// SMEM: ws64 12*512*8 = 49152, h 2*128*4 = 1024, gact 512*4 = 2048 -> 52224B
// ---------------------------------------------------------------------------
__global__ __launch_bounds__(256, 1) void lstm_kernel(
    const float* __restrict__ Whh, const float* __restrict__ h0,
    const float* __restrict__ c0, float* __restrict__ out)
{
    extern __shared__ char sm2c[];
    u64*   ws64 = (u64*)sm2c;                       // [NSK][512]
    float* h_s  = (float*)(sm2c + NSK * 512 * 8);   // [2][128]
    float* gact = h_s + 2 * HH;                     // [512] activated gates

    const int tid = threadIdx.x;          // 0..255
    const int jh  = tid & 127;            // hidden unit index
    const int b   = blockIdx.x;
    const int rA  = tid;                  // row A: i (tid<128) or f
    const int rB  = tid + 256;            // row B: g (tid<128) or o

    // --- register weights: rows rA, rB cols [0,104) as 52 u64 each ---
    u64 wA[REGK / 2], wB[REGK / 2];
    {
        const float* a = Whh + rA * HH;
        const float* bq = Whh + rB * HH;
        #pragma unroll
        for (int q = 0; q < REGK / 4; q++) {
            float4 v = *(const float4*)&a[4 * q];
            wA[2 * q] = pk(v.x, v.y); wA[2 * q + 1] = pk(v.z, v.w);
            float4 w = *(const float4*)&bq[4 * q];
            wB[2 * q] = pk(w.x, w.y); wB[2 * q + 1] = pk(w.z, w.w);
        }
    }
    // --- SMEM weights: ws64[kk*512 + r] = {W[r][104+2kk], W[r][105+2kk]} ---
    for (int idx = tid; idx < NSK * 512; idx += 256) {
        int kk = idx >> 9, r = idx & 511;
        float2 v = *(const float2*)&Whh[r * HH + REGK + 2 * kk];
        ws64[idx] = pk(v.x, v.y);
    }
    // --- initial state (both partner threads carry c redundantly) ---
    float c = c0[b * HH + jh];
    if (tid < HH) h_s[tid] = h0[b * HH + tid];
    __syncthreads();

    const float* xp = g_xproj + (size_t)b * TT * GG;
    float* enc = out + BB * HH + (size_t)b * TT * HH;

    int p = 0;
    float xgA = xp[rA];                    // prefetch t = 0
    float xgB = xp[rB];
    for (int t = 0; t < TT; t++) {
        float xa = xgA, xb = xgB;
        if (t + 1 < TT) {                  // prefetch next step
            xgA = xp[(size_t)(t + 1) * GG + rA];
            xgB = xp[(size_t)(t + 1) * GG + rB];
        }

        const u64* hb64 = (const u64*)&h_s[p * HH];   // 64 h pairs
        u64 aA0 = 0ULL, aA1 = 0ULL, aB0 = 0ULL, aB1 = 0ULL;

        // register part: k in [0, 104)
        #pragma unroll
        for (int kk = 0; kk < REGK / 2; kk++) {
            u64 hh = hb64[kk];                         // LDS.64 broadcast
            if (kk & 1) { fma2(aA1, wA[kk], hh); fma2(aB1, wB[kk], hh); }
            else        { fma2(aA0, wA[kk], hh); fma2(aB0, wB[kk], hh); }
        }
        // SMEM part: k in [104, 128)
        #pragma unroll
        for (int kk = 0; kk < NSK; kk++) {
            u64 hh = hb64[REGK / 2 + kk];
            u64 wsa = ws64[kk * 512 + rA];
            u64 wsb = ws64[kk * 512 + rB];
            if (kk & 1) { fma2(aA1, wsa, hh); fma2(aB1, wsb, hh); }
            else        { fma2(aA0, wsa, hh); fma2(aB0, wsb, hh); }
        }

        float s0, s1, s2, s3;
        upk(aA0, s0, s1); upk(aA1, s2, s3);
        float gA = xa + (s0 + s1) + (s2 + s3);
        upk(aB0, s0, s1); upk(aB1, s2, s3);
        float gB = xb + (s0 + s1) + (s2 + s3);

        // distributed activations: rows 0-255 = i/f (sigmoid),
        // rows 256-383 = g (tanh), 384-511 = o (sigmoid)
        float act0 = sigmoidf_(gA);
        float act1 = (tid < 128) ? tanhf_(gB) : sigmoidf_(gB);
        gact[tid] = act0;
        gact[256 + tid] = act1;
        __syncthreads();

        // phase B (redundant across the partner pair; c stays consistent)
        float ig = gact[jh];
        float fg = gact[jh + 128];
        float gg = gact[256 + jh];
        float og = gact[384 + jh];
        c = fg * c + ig * gg;
        if (tid < 128) {
            float hn = og * tanhf_(c);
            h_s[(p ^ 1) * HH + jh] = hn;
            enc[(size_t)t * HH + jh] = hn;
        }
        __syncthreads();
        p ^= 1;
    }

    if (tid < HH) out[b * HH + tid] = h_s[p * HH + tid];   // h_last
}

extern "C" void kernel_launch(void* const* d_in, const int* in_sizes, int n_in,
                              void* d_out, int out_size) {
    const float* x    = (const float*)d_in[0];   // [B,T,I]
    const float* h0   = (const float*)d_in[1];   // [B,H]
    const float* c0   = (const float*)d_in[2];   // [B,H]
    const float* Wih  = (const float*)d_in[3];   // [4H,I]
    const float* Whh  = (const float*)d_in[4];   // [4H,H]
    const float* bih  = (const float*)d_in[5];   // [4H]
    const float* bhh  = (const float*)d_in[6];   // [4H]
    float* out = (float*)d_out;                  // [B*H] h_last, then [B,T,H]

    constexpr int SMEM1 = (64 * 512 + 512 + 64 * 68) * 4;        // 150528
    constexpr int SMEM2 = NSK * 512 * 8 + 2 * HH * 4 + 512 * 4;  // 52224

    cudaFuncSetAttribute(xproj_kernel,
        cudaFuncAttributeMaxDynamicSharedMemorySize, SMEM1);
    cudaFuncSetAttribute(lstm_kernel,
        cudaFuncAttributeMaxDynamicSharedMemorySize, SMEM2);

    xproj_kernel<<<148, 512, SMEM1>>>(x, Wih, bih, bhh);
    lstm_kernel<<<BB, 256, SMEM2>>>(Whh, h0, c0, out);
}

// round 10
// speedup vs baseline: 1.5242x; 1.0276x over previous
#include <cuda_runtime.h>
#include <cuda_bf16.h>
#include <cstdint>
#include <cstddef>

#define BB 128
#define TT 2048
#define II 64
#define HH 128
#define GG 512                 // 4*H
#define BT (BB * TT)

// ---- recurrence config: 256 threads, 2 rows/thread --------------------------
#define REGK 104               // W_hh cols per row held in registers
#define SMEMK (HH - REGK)      // 24 cols in SMEM
#define NSQ (SMEMK / 4)        // 6 ulonglong2 groups per row

typedef unsigned long long u64;

// 512MB scratch for x_proj[row][g], row = b*T + t, g in [0,512)
__device__ float g_xproj[(size_t)BT * GG];

__device__ __forceinline__ u64 pk(float lo, float hi) {
    u64 r; asm("mov.b64 %0,{%1,%2};" : "=l"(r) : "f"(lo), "f"(hi)); return r;
}
__device__ __forceinline__ void upk(u64 v, float& lo, float& hi) {
    asm("mov.b64 {%0,%1},%2;" : "=f"(lo), "=f"(hi) : "l"(v));
}
// packed fp32x2 FMA (sm_103a): d.lo += a.lo*b.lo ; d.hi += a.hi*b.hi
__device__ __forceinline__ void fma2(u64& d, u64 a, u64 b) {
    asm("fma.rn.f32x2 %0,%1,%2,%0;" : "+l"(d) : "l"(a), "l"(b));
}

__device__ __forceinline__ float sigmoidf_(float x) {
    return 1.0f / (1.0f + __expf(-x));
}
__device__ __forceinline__ float tanhf_(float x) {
    float xc = fminf(fmaxf(x, -15.0f), 15.0f);
    float e = __expf(-2.0f * xc);
    return (1.0f - e) / (1.0f + e);
}

// ---------------------------------------------------------------------------
// Phase 1: g_xproj[row][512] = W_ih @ x[row] + (b_ih + b_hh)
// Persistent CTAs; W_ih k-major in SMEM; 64-row x tiles k-major in SMEM.
// Each thread: 8 rows x 8 cols via packed f32x2 FMA.
// ---------------------------------------------------------------------------
__global__ __launch_bounds__(512, 1) void xproj_kernel(
    const float* __restrict__ x, const float* __restrict__ Wih,
    const float* __restrict__ bih, const float* __restrict__ bhh)
{
    extern __shared__ float sm1[];
    float* wsg  = sm1;                   // [64][512] k-major
    float* bsum = wsg + 64 * 512;        // [512]
    float* xs   = bsum + 512;            // [64 k][68 rows] padded

    const int tid = threadIdx.x;

    for (int idx = tid; idx < 64 * 512; idx += 512) {
        int k = idx >> 9, c = idx & 511;
        wsg[idx] = Wih[c * 64 + k];
    }
    bsum[tid] = bih[tid] + bhh[tid];
    __syncthreads();

    const int lane = tid & 31, wrp = tid >> 5;
    const int r0 = (wrp & 7) * 8;
    const int cb = (wrp >> 3) * 256 + lane * 4;

    u64 bp[4];
    {
        float4 t0 = *(const float4*)&bsum[cb];
        float4 t1 = *(const float4*)&bsum[cb + 128];
        bp[0] = pk(t0.x, t0.y); bp[1] = pk(t0.z, t0.w);
        bp[2] = pk(t1.x, t1.y); bp[3] = pk(t1.z, t1.w);
    }

    for (int tile = blockIdx.x; tile < BT / 64; tile += gridDim.x) {
        __syncthreads();
        for (int idx = tid; idx < 64 * 64; idx += 512) {
            int r = idx >> 6, k = idx & 63;
            xs[k * 68 + r] = x[(size_t)tile * 64 * 64 + idx];
        }
        __syncthreads();

        u64 acc[8][4];
        #pragma unroll
        for (int ri = 0; ri < 8; ri++) {
            acc[ri][0] = bp[0]; acc[ri][1] = bp[1];
            acc[ri][2] = bp[2]; acc[ri][3] = bp[3];
        }

        #pragma unroll 8
        for (int k = 0; k < 64; k++) {
            float4 w0 = *(const float4*)&wsg[k * 512 + cb];
            float4 w1 = *(const float4*)&wsg[k * 512 + cb + 128];
            u64 wa = pk(w0.x, w0.y), wb = pk(w0.z, w0.w);
            u64 wc = pk(w1.x, w1.y), wd = pk(w1.z, w1.w);
            float4 xa = *(const float4*)&xs[k * 68 + r0];
            float4 xb = *(const float4*)&xs[k * 68 + r0 + 4];
            float xv[8] = {xa.x, xa.y, xa.z, xa.w, xb.x, xb.y, xb.z, xb.w};
            #pragma unroll
            for (int ri = 0; ri < 8; ri++) {
                u64 xx = pk(xv[ri], xv[ri]);
                fma2(acc[ri][0], wa, xx); fma2(acc[ri][1], wb, xx);
                fma2(acc[ri][2], wc, xx); fma2(acc[ri][3], wd, xx);
            }
        }

        #pragma unroll
        for (int ri = 0; ri < 8; ri++) {
            size_t row = (size_t)tile * 64 + r0 + ri;
            float a0,a1,a2,a3,a4,a5,a6,a7;
            upk(acc[ri][0], a0, a1); upk(acc[ri][1], a2, a3);
            upk(acc[ri][2], a4, a5); upk(acc[ri][3], a6, a7);
            *(float4*)&g_xproj[row * GG + cb]       = make_float4(a0,a1,a2,a3);
            *(float4*)&g_xproj[row * GG + cb + 128] = make_float4(a4,a5,a6,a7);
        }
    }
}

// ---------------------------------------------------------------------------
// Phase 2: LSTM recurrence. One CTA per batch (128 CTAs, one wave).
// 256 threads; thread tid owns gate rows tid and tid+256; threads tid and
// tid+128 together hold all 4 gates of hidden unit jh = tid & 127.
// W_hh[row][0:104] in registers (2 x 52 u64); [104:128) in SMEM as
// ulonglong2 [6][512] -> 12 LDS.128/thread. h broadcast as LDS.128 pairs.
// Activations packed as float2: gAB[jh]={i,g}, gAB[128+jh]={f,o}.
// SMEM: ws2 6*512*16 = 49152, h 2*128*4 = 1024, gAB 256*8 = 2048 -> 52224B
// ---------------------------------------------------------------------------
__global__ __launch_bounds__(256, 1) void lstm_kernel(
    const float* __restrict__ Whh, const float* __restrict__ h0,
    const float* __restrict__ c0, float* __restrict__ out)
{
    extern __shared__ char sm2c[];
    ulonglong2* ws2 = (ulonglong2*)sm2c;                 // [NSQ][512]
    float*      h_s = (float*)(sm2c + NSQ * 512 * 16);   // [2][128]
    float2*     gAB = (float2*)(h_s + 2 * HH);           // [256]

    const int tid = threadIdx.x;          // 0..255
    const int jh  = tid & 127;            // hidden unit index
    const int b   = blockIdx.x;
    const int rA  = tid;                  // row A: i (tid<128) or f
    const int rB  = tid + 256;            // row B: g (tid<128) or o

    // --- register weights: rows rA, rB cols [0,104) as 52 u64 each ---
    u64 wA[REGK / 2], wB[REGK / 2];
    {
        const float* a  = Whh + rA * HH;
        const float* bq = Whh + rB * HH;
        #pragma unroll
        for (int q = 0; q < REGK / 4; q++) {
            float4 v = *(const float4*)&a[4 * q];
            wA[2 * q] = pk(v.x, v.y); wA[2 * q + 1] = pk(v.z, v.w);
            float4 w = *(const float4*)&bq[4 * q];
            wB[2 * q] = pk(w.x, w.y); wB[2 * q + 1] = pk(w.z, w.w);
        }
    }
    // --- SMEM weights: ws2[q*512 + r] = cols [104+4q, 104+4q+3] of row r ---
    for (int idx = tid; idx < NSQ * 512; idx += 256) {
        int q = idx >> 9, r = idx & 511;
        float4 v = *(const float4*)&Whh[r * HH + REGK + 4 * q];
        ulonglong2 u; u.x = pk(v.x, v.y); u.y = pk(v.z, v.w);
        ws2[idx] = u;
    }
    // --- initial state (both partner threads carry c redundantly) ---
    float c = c0[b * HH + jh];
    if (tid < HH) h_s[tid] = h0[b * HH + tid];
    __syncthreads();

    const float* xp = g_xproj + (size_t)b * TT * GG;
    float* enc = out + BB * HH + (size_t)b * TT * HH;

    int p = 0;
    float xgA = xp[rA];                    // prefetch t = 0
    float xgB = xp[rB];
    for (int t = 0; t < TT; t++) {
        float xa = xgA, xb = xgB;
        if (t + 1 < TT) {                  // prefetch next step
            xgA = xp[(size_t)(t + 1) * GG + rA];
            xgB = xp[(size_t)(t + 1) * GG + rB];
        }

        const ulonglong2* hb2 = (const ulonglong2*)&h_s[p * HH];  // 32 pairs
        u64 aA0 = 0ULL, aA1 = 0ULL, aB0 = 0ULL, aB1 = 0ULL;

        // register part: k in [0, 104) -> 26 LDS.128 broadcasts
        #pragma unroll
        for (int q = 0; q < REGK / 4; q++) {
            ulonglong2 hh = hb2[q];
            fma2(aA0, wA[2 * q],     hh.x); fma2(aB0, wB[2 * q],     hh.x);
            fma2(aA1, wA[2 * q + 1], hh.y); fma2(aB1, wB[2 * q + 1], hh.y);
        }
        // SMEM part: k in [104, 128) -> 6 broadcasts + 12 weight LDS.128
        #pragma unroll
        for (int q = 0; q < NSQ; q++) {
            ulonglong2 hh = hb2[REGK / 4 + q];
            ulonglong2 wa = ws2[q * 512 + rA];
            ulonglong2 wb = ws2[q * 512 + rB];
            fma2(aA0, wa.x, hh.x); fma2(aA1, wa.y, hh.y);
            fma2(aB0, wb.x, hh.x); fma2(aB1, wb.y, hh.y);
        }

        float s0, s1, s2, s3;
        upk(aA0, s0, s1); upk(aA1, s2, s3);
        float gA = xa + (s0 + s1) + (s2 + s3);
        upk(aB0, s0, s1); upk(aB1, s2, s3);
        float gB = xb + (s0 + s1) + (s2 + s3);

        // distributed activations, packed for the phase-B gather:
        // tid<128: rows (i, g) -> gAB[jh] = {sig(gA), tanh(gB)}
        // tid>=128: rows (f, o) -> gAB[128+jh] = {sig(gA), sig(gB)}
        float act0 = sigmoidf_(gA);
        float act1 = (tid < 128) ? tanhf_(gB) : sigmoidf_(gB);
        gAB[tid] = make_float2(act0, act1);
        __syncthreads();

        // phase B (redundant across the partner pair; c stays consistent)
        float2 vig = gAB[jh];          // {i, g}
        float2 vfo = gAB[128 + jh];    // {f, o}
        c = vfo.x * c + vig.x * vig.y;
        if (tid < 128) {
            float hn = vfo.y * tanhf_(c);
            h_s[(p ^ 1) * HH + jh] = hn;
            enc[(size_t)t * HH + jh] = hn;
        }
        __syncthreads();
        p ^= 1;
    }

    if (tid < HH) out[b * HH + tid] = h_s[p * HH + tid];   // h_last
}

extern "C" void kernel_launch(void* const* d_in, const int* in_sizes, int n_in,
                              void* d_out, int out_size) {
    const float* x    = (const float*)d_in[0];   // [B,T,I]
    const float* h0   = (const float*)d_in[1];   // [B,H]
    const float* c0   = (const float*)d_in[2];   // [B,H]
    const float* Wih  = (const float*)d_in[3];   // [4H,I]
    const float* Whh  = (const float*)d_in[4];   // [4H,H]
    const float* bih  = (const float*)d_in[5];   // [4H]
    const float* bhh  = (const float*)d_in[6];   // [4H]
    float* out = (float*)d_out;                  // [B*H] h_last, then [B,T,H]

    constexpr int SMEM1 = (64 * 512 + 512 + 64 * 68) * 4;          // 150528
    constexpr int SMEM2 = NSQ * 512 * 16 + 2 * HH * 4 + 256 * 8;   // 52224

    cudaFuncSetAttribute(xproj_kernel,
        cudaFuncAttributeMaxDynamicSharedMemorySize, SMEM1);
    cudaFuncSetAttribute(lstm_kernel,
        cudaFuncAttributeMaxDynamicSharedMemorySize, SMEM2);

    xproj_kernel<<<148, 512, SMEM1>>>(x, Wih, bih, bhh);
    lstm_kernel<<<BB, 256, SMEM2>>>(Whh, h0, c0, out);
}